// round 13
// baseline (speedup 1.0000x reference)
#include <cuda_runtime.h>
#include <cuda_bf16.h>
#include <cstdint>
#include <cstddef>

#define B_    2048
#define T_    200
#define H1_   80
#define H2_   40
#define NROWS (B_*T_)        // 409600
#define NT1   (NROWS/128)    // 3200 k1 tiles (128 rows)
#define NT2   (NROWS/128)    // 3200 k2 tiles (128 rows)
#define PG1   296
#define PG2   444
#define PADV  (-4294967296.0f)

// ---------------- device scratch ----------------
__device__ float g_h1[(size_t)NROWS*H1_];
__device__ float g_h2[(size_t)NROWS*H2_];
__device__ float g_qb[B_*H1_];
__device__ float g_part1[NT1*2*H1_];
__device__ float g_part2[NT2*2*H2_];
__device__ float g_m1[H1_], g_r1[H1_];
__device__ float g_m2[H2_], g_r2[H2_];
__device__ int   g_mask_mode;
// fragment-packed bf16 weight images (word = n*stride + ks*8 + t*2 + h)
__device__ __align__(16) uint32_t g_B1h[80*72], g_B1l[80*72];
__device__ __align__(16) uint32_t g_B2h[40*40], g_B2l[40*40];

// ---------------- helpers ----------------
__device__ __forceinline__ uint32_t smem_u32(const void* p) {
    uint32_t a;
    asm("{ .reg .u64 t; cvta.to.shared.u64 t, %1; cvt.u32.u64 %0, t; }"
        : "=r"(a) : "l"(p));
    return a;
}
__device__ __forceinline__ void lds64(uint32_t a, uint32_t& v0, uint32_t& v1) {
    asm volatile("ld.shared.v2.b32 {%0,%1}, [%2];" : "=r"(v0), "=r"(v1) : "r"(a));
}
__device__ __forceinline__ void pf_l2(const void* p) {
    asm volatile("prefetch.global.L2 [%0];" :: "l"(p));
}
__device__ __forceinline__ uint32_t pack_bf(float x0, float x1) { // x0 -> low
    uint32_t r;
    asm("cvt.rn.bf16x2.f32 %0, %1, %2;" : "=r"(r) : "f"(x1), "f"(x0));
    return r;
}
// truncation split: hi = x & 0xffff0000 (one PRMT packs both), lo = x - hi (exact)
__device__ __forceinline__ void cvt_hilo(float x0, float x1,
                                         uint32_t& hi, uint32_t& lo) {
    uint32_t u0 = __float_as_uint(x0), u1 = __float_as_uint(x1);
    hi = __byte_perm(u0, u1, 0x7632);
    float h0 = __uint_as_float(u0 & 0xffff0000u);
    float h1 = __uint_as_float(u1 & 0xffff0000u);
    lo = pack_bf(x0 - h0, x1 - h1);
}
__device__ __forceinline__ void mma_bf16(float* c,
                                         uint32_t a0, uint32_t a1, uint32_t a2, uint32_t a3,
                                         uint32_t b0, uint32_t b1) {
    asm volatile(
        "mma.sync.aligned.m16n8k16.row.col.f32.bf16.bf16.f32 "
        "{%0,%1,%2,%3}, {%4,%5,%6,%7}, {%8,%9}, {%0,%1,%2,%3};"
        : "+f"(c[0]), "+f"(c[1]), "+f"(c[2]), "+f"(c[3])
        : "r"(a0), "r"(a1), "r"(a2), "r"(a3), "r"(b0), "r"(b1));
}
__device__ __forceinline__ float dice1f(float v, float m, float r, float a) {
    float xn = (v - m) * r;
    float p  = 1.f / (1.f + __expf(-xn));
    return v * (a + p * (1.f - a));
}
__device__ __forceinline__ void frag_loc(int d, int& wof, int& pos) {
    int ks = d >> 4, kk = d & 15;
    int h = (kk >= 8) ? 1 : 0;
    int t = (kk & 7) >> 1;
    wof = ks * 8 + t * 2 + h;
    pos = kk & 1;
}

// ---------------- prep_all ----------------
__global__ void __launch_bounds__(256)
prep_all(const float* __restrict__ queries, const float* __restrict__ W1,
         const float* __restrict__ W2, const float* __restrict__ b1,
         const unsigned char* __restrict__ mask) {
    int blk = blockIdx.x, tid = threadIdx.x;
    if (blk < 40) {
        int i = blk * 256 + tid;
        int n = i >> 7, d = i & 127;
        float w;
        if (d < 64) w = W1[(64 + d) * H1_ + n] - W1[(128 + d) * H1_ + n];
        else        w = W1[(128 + d) * H1_ + n];
        __nv_bfloat16 h = __float2bfloat16(w);
        int wof, pos; frag_loc(d, wof, pos);
        *((__nv_bfloat16*)(g_B1h + n * 72 + wof) + pos) = h;
        *((__nv_bfloat16*)(g_B1l + n * 72 + wof) + pos) =
            __float2bfloat16(w - __bfloat162float(h));
    } else if (blk < 53) {
        int i = (blk - 40) * 256 + tid;
        if (i < H2_ * H1_) {
            int n = i / H1_, d = i - n * H1_;
            float w = W2[d * H2_ + n];
            __nv_bfloat16 h = __float2bfloat16(w);
            int wof, pos; frag_loc(d, wof, pos);
            *((__nv_bfloat16*)(g_B2h + n * 40 + wof) + pos) = h;
            *((__nv_bfloat16*)(g_B2l + n * 40 + wof) + pos) =
                __float2bfloat16(w - __bfloat162float(h));
        }
    } else if (blk == 53) {
        __shared__ int s_f32ok, s_i32ok, s_f32one, s_i32one;
        if (tid == 0) { s_f32ok = 1; s_i32ok = 1; s_f32one = 0; s_i32one = 0; }
        __syncthreads();
        const unsigned* w = (const unsigned*)mask;
        int f32ok = 1, i32ok = 1, f32one = 0, i32one = 0;
        for (int i = tid; i < 1024; i += 256) {
            unsigned v = w[i];
            if (v != 0u && v != 0x3F800000u) f32ok = 0;
            if (v == 0x3F800000u) f32one = 1;
            if (v != 0u && v != 1u) i32ok = 0;
            if (v == 1u) i32one = 1;
        }
        if (!f32ok) atomicAnd(&s_f32ok, 0);
        if (f32one) atomicOr(&s_f32one, 1);
        if (!i32ok) atomicAnd(&s_i32ok, 0);
        if (i32one) atomicOr(&s_i32one, 1);
        __syncthreads();
        if (tid == 0) {
            int mode = 0;
            if (s_f32ok && s_f32one)      mode = 2;
            else if (s_i32ok && s_i32one) mode = 1;
            g_mask_mode = mode;
        }
    } else {
        // qb: 16 batches per block, Wq staged once
        __shared__ float wq[64 * 80];
        __shared__ float qs[16][64];
        __shared__ float sb1[H1_];
        int pair = blk - 54;
        for (int i = tid; i < 64 * 80; i += 256)
            wq[i] = W1[i] + W1[128 * 80 + i];
        for (int i = tid; i < 16 * 64; i += 256)
            qs[i >> 6][i & 63] = queries[(size_t)(pair * 16) * 64 + i];
        if (tid < H1_) sb1[tid] = b1[tid];
        __syncthreads();
        #pragma unroll
        for (int w = 0; w < 5; ++w) {
            int work = tid + w * 256;
            int j = work / H1_, h = work - j * H1_;
            float acc = sb1[h];
            #pragma unroll 8
            for (int d = 0; d < 64; ++d)
                acc += qs[j][d] * wq[d * 80 + h];
            g_qb[(pair * 16 + j) * H1_ + h] = acc;
        }
    }
}

// ---------------- K1: persistent, warp = 16 rows x 80 cols, 2 CTA/SM ----------------
// dyn smem: B_hi@0 (23040), B_lo@23040, red@46080 (2*8*160*4 = 10240) => 56320
#define K1_BLO  23040
#define K1_RED  46080
#define K1_SMEM 56320

__global__ void __launch_bounds__(256, 2)
k1(const float* __restrict__ keys, const float* __restrict__ queries) {
    extern __shared__ __align__(16) unsigned char smem[];
    uint32_t sb = smem_u32(smem);
    int tid = threadIdx.x, wid = tid >> 5, lid = tid & 31;
    int g = lid >> 2, t = lid & 3;

    {
        const uint4* s0 = (const uint4*)g_B1h;
        const uint4* s1 = (const uint4*)g_B1l;
        uint4* d0 = (uint4*)smem;
        uint4* d1 = (uint4*)(smem + K1_BLO);
        for (int i = tid; i < 1440; i += 256) { d0[i] = s0[i]; d1[i] = s1[i]; }
    }
    float* red = (float*)(smem + K1_RED);
    __syncthreads();

    int par = 0;
    for (int tile = blockIdx.x; tile < NT1; tile += PG1) {
        int row0 = tile * 128;
        int r0 = row0 + wid * 16 + g, r1 = r0 + 8;
        int br0 = r0 / T_, br1 = r1 / T_;
        const float* k0p = keys + (size_t)r0 * 64;
        const float* k1p = keys + (size_t)r1 * 64;
        const float* q0p = queries + (size_t)br0 * 64;
        const float* q1p = queries + (size_t)br1 * 64;

        // L2 prefetch: this tile's second key lines + next tile's first lines
        pf_l2(k0p + 32); pf_l2(k1p + 32);
        {
            int tn = tile + PG1;
            if (tn < NT1) {
                int rn = tn * 128 + wid * 16 + g;
                pf_l2(keys + (size_t)rn * 64);
                pf_l2(keys + (size_t)(rn + 8) * 64);
            }
        }

        float acc[10][4];
        #pragma unroll
        for (int nt = 0; nt < 10; ++nt)
            #pragma unroll
            for (int j = 0; j < 4; ++j) acc[nt][j] = 0.f;

        uint32_t bbase = sb + (uint32_t)g * 288 + t * 8;

        #pragma unroll
        for (int j = 0; j < 4; ++j) {
            int c0 = 2 * t + 16 * j, c1 = c0 + 8;
            float2 k00 = *(const float2*)(k0p + c0);
            float2 k02 = *(const float2*)(k0p + c1);
            float2 k10 = *(const float2*)(k1p + c0);
            float2 k12 = *(const float2*)(k1p + c1);
            #pragma unroll
            for (int half = 0; half < 2; ++half) {
                uint32_t ah0, al0, ah1, al1, ah2, al2, ah3, al3;
                if (half == 0) {
                    cvt_hilo(k00.x, k00.y, ah0, al0);
                    cvt_hilo(k10.x, k10.y, ah1, al1);
                    cvt_hilo(k02.x, k02.y, ah2, al2);
                    cvt_hilo(k12.x, k12.y, ah3, al3);
                } else {
                    float2 w00 = *(const float2*)(q0p + c0);
                    float2 w02 = *(const float2*)(q0p + c1);
                    float2 w10 = *(const float2*)(q1p + c0);
                    float2 w12 = *(const float2*)(q1p + c1);
                    cvt_hilo(k00.x * w00.x, k00.y * w00.y, ah0, al0);
                    cvt_hilo(k10.x * w10.x, k10.y * w10.y, ah1, al1);
                    cvt_hilo(k02.x * w02.x, k02.y * w02.y, ah2, al2);
                    cvt_hilo(k12.x * w12.x, k12.y * w12.y, ah3, al3);
                }
                uint32_t bks = bbase + (j + 4 * half) * 32;
                #pragma unroll
                for (int nt = 0; nt < 10; ++nt) {
                    uint32_t bh0, bh1, bl0, bl1;
                    lds64(bks + nt * 2304, bh0, bh1);
                    lds64(bks + nt * 2304 + K1_BLO, bl0, bl1);
                    mma_bf16(acc[nt], ah0, ah1, ah2, ah3, bh0, bh1);
                    mma_bf16(acc[nt], ah0, ah1, ah2, ah3, bl0, bl1);
                    mma_bf16(acc[nt], al0, al1, al2, al3, bh0, bh1);
                }
            }
        }

        // epilogue: qb add, STG h1, column stats
        float s[20], ss[20];
        const float* qb0 = g_qb + br0 * H1_;
        const float* qb1 = g_qb + br1 * H1_;
        #pragma unroll
        for (int nt = 0; nt < 10; ++nt) {
            int col = nt * 8 + 2 * t;
            float2 qa = *(const float2*)(qb0 + col);
            float2 qc = *(const float2*)(qb1 + col);
            float v00 = acc[nt][0] + qa.x, v01 = acc[nt][1] + qa.y;
            float v10 = acc[nt][2] + qc.x, v11 = acc[nt][3] + qc.y;
            float2 o0; o0.x = v00; o0.y = v01;
            float2 o1; o1.x = v10; o1.y = v11;
            *(float2*)(g_h1 + (size_t)r0 * H1_ + col) = o0;
            *(float2*)(g_h1 + (size_t)r1 * H1_ + col) = o1;
            s[2 * nt]      = v00 + v10;
            ss[2 * nt]     = v00 * v00 + v10 * v10;
            s[2 * nt + 1]  = v01 + v11;
            ss[2 * nt + 1] = v01 * v01 + v11 * v11;
        }
        #pragma unroll
        for (int jj = 0; jj < 20; ++jj) {
            #pragma unroll
            for (int off = 4; off <= 16; off <<= 1) {
                s[jj]  += __shfl_xor_sync(0xffffffffu, s[jj],  off);
                ss[jj] += __shfl_xor_sync(0xffffffffu, ss[jj], off);
            }
        }
        float* rp = red + par * 1280 + wid * 160;
        if (lid < 4) {
            #pragma unroll
            for (int nt = 0; nt < 10; ++nt) {
                int col = nt * 8 + 2 * lid;
                rp[col]          = s[2 * nt];
                rp[col + 1]      = s[2 * nt + 1];
                rp[80 + col]     = ss[2 * nt];
                rp[80 + col + 1] = ss[2 * nt + 1];
            }
        }
        __syncthreads();
        if (tid < H1_) {
            float S = 0.f, SS = 0.f;
            #pragma unroll
            for (int w = 0; w < 8; ++w) {
                S  += red[par * 1280 + w * 160 + tid];
                SS += red[par * 1280 + w * 160 + 80 + tid];
            }
            g_part1[tile * 160 + tid]      = S;
            g_part1[tile * 160 + 80 + tid] = SS;
        }
        par ^= 1;
    }
}

// ---------------- stats ----------------
__global__ void stats1() {
    __shared__ float rs[256], rss[256];
    int h = blockIdx.x, tid = threadIdx.x;
    float S = 0.f, SS = 0.f;
    for (int k = tid; k < NT1; k += 256) {
        S  += g_part1[k * 160 + h];
        SS += g_part1[k * 160 + 80 + h];
    }
    rs[tid] = S; rss[tid] = SS;
    __syncthreads();
    for (int st = 128; st > 0; st >>= 1) {
        if (tid < st) { rs[tid] += rs[tid + st]; rss[tid] += rss[tid + st]; }
        __syncthreads();
    }
    if (tid == 0) {
        float mean = rs[0] / (float)NROWS;
        float var  = rss[0] / (float)NROWS - mean * mean;
        g_m1[h] = mean;
        g_r1[h] = rsqrtf(fmaxf(var, 0.f) + 1e-8f);
    }
}
__global__ void stats2() {
    __shared__ float rs[256], rss[256];
    int h = blockIdx.x, tid = threadIdx.x;
    float S = 0.f, SS = 0.f;
    for (int k = tid; k < NT2; k += 256) {
        S  += g_part2[k * 80 + h];
        SS += g_part2[k * 80 + 40 + h];
    }
    rs[tid] = S; rss[tid] = SS;
    __syncthreads();
    for (int st = 128; st > 0; st >>= 1) {
        if (tid < st) { rs[tid] += rs[tid + st]; rss[tid] += rss[tid + st]; }
        __syncthreads();
    }
    if (tid == 0) {
        float mean = rs[0] / (float)NROWS;
        float var  = rss[0] / (float)NROWS - mean * mean;
        g_m2[h] = mean;
        g_r2[h] = rsqrtf(fmaxf(var, 0.f) + 1e-8f);
    }
}

// ---------------- K2: persistent, warp = 16 rows x 40 cols (3 CTA/SM) ----------------
// dyn smem: B2_hi@0 (6400), B2_lo@6400, red@12800 (2*8*80*4 = 5120) => 17920
#define K2_BLO  6400
#define K2_RED  12800
#define K2_SMEM 17920

__global__ void __launch_bounds__(256, 3)
k2(const float* __restrict__ b2, const float* __restrict__ a1) {
    extern __shared__ __align__(16) unsigned char smem[];
    __shared__ float pm[H1_], pr[H1_], pa[H1_], sb2[H2_];
    uint32_t sb = smem_u32(smem);
    int tid = threadIdx.x, wid = tid >> 5, lid = tid & 31;
    int g = lid >> 2, t = lid & 3;

    {
        const uint4* s0 = (const uint4*)g_B2h;
        const uint4* s1 = (const uint4*)g_B2l;
        uint4* d0 = (uint4*)smem;
        uint4* d1 = (uint4*)(smem + K2_BLO);
        for (int i = tid; i < 400; i += 256) { d0[i] = s0[i]; d1[i] = s1[i]; }
    }
    if (tid < H1_) { pm[tid] = g_m1[tid]; pr[tid] = g_r1[tid]; pa[tid] = a1[tid]; }
    if (tid >= 128 && tid < 128 + H2_) sb2[tid - 128] = b2[tid - 128];
    float* red = (float*)(smem + K2_RED);
    __syncthreads();

    // L2 prefetch: first tile's h1 lines
    {
        int r0 = blockIdx.x * 128 + wid * 16 + g;
        const float* h0 = g_h1 + (size_t)r0 * H1_;
        const float* h1 = g_h1 + (size_t)(r0 + 8) * H1_;
        pf_l2(h0); pf_l2(h0 + 32); pf_l2(h0 + 64);
        pf_l2(h1); pf_l2(h1 + 32); pf_l2(h1 + 64);
    }

    int par = 0;
    for (int tile = blockIdx.x; tile < NT2; tile += PG2) {
        int row0 = tile * 128;
        int r0 = row0 + wid * 16 + g, r1 = r0 + 8;
        const float* h0p = g_h1 + (size_t)r0 * H1_;
        const float* h1p = g_h1 + (size_t)r1 * H1_;

        // L2 prefetch next tile's h1 lines (3 lines x 2 rows)
        {
            int tn = tile + PG2;
            if (tn < NT2) {
                int rn = tn * 128 + wid * 16 + g;
                const float* n0 = g_h1 + (size_t)rn * H1_;
                const float* n1 = g_h1 + (size_t)(rn + 8) * H1_;
                pf_l2(n0); pf_l2(n0 + 32); pf_l2(n0 + 64);
                pf_l2(n1); pf_l2(n1 + 32); pf_l2(n1 + 64);
            }
        }

        float acc[5][4];
        #pragma unroll
        for (int nt = 0; nt < 5; ++nt)
            #pragma unroll
            for (int j = 0; j < 4; ++j) acc[nt][j] = 0.f;

        uint32_t bbase = sb + (uint32_t)g * 160 + t * 8;

        #pragma unroll
        for (int ks = 0; ks < 5; ++ks) {
            int c0 = 2 * t + 16 * ks, c1 = c0 + 8;
            float2 x00 = *(const float2*)(h0p + c0);
            float2 x02 = *(const float2*)(h0p + c1);
            float2 x10 = *(const float2*)(h1p + c0);
            float2 x12 = *(const float2*)(h1p + c1);
            x00.x = dice1f(x00.x, pm[c0],     pr[c0],     pa[c0]);
            x00.y = dice1f(x00.y, pm[c0 + 1], pr[c0 + 1], pa[c0 + 1]);
            x02.x = dice1f(x02.x, pm[c1],     pr[c1],     pa[c1]);
            x02.y = dice1f(x02.y, pm[c1 + 1], pr[c1 + 1], pa[c1 + 1]);
            x10.x = dice1f(x10.x, pm[c0],     pr[c0],     pa[c0]);
            x10.y = dice1f(x10.y, pm[c0 + 1], pr[c0 + 1], pa[c0 + 1]);
            x12.x = dice1f(x12.x, pm[c1],     pr[c1],     pa[c1]);
            x12.y = dice1f(x12.y, pm[c1 + 1], pr[c1 + 1], pa[c1 + 1]);
            uint32_t ah0, al0, ah1, al1, ah2, al2, ah3, al3;
            cvt_hilo(x00.x, x00.y, ah0, al0);
            cvt_hilo(x10.x, x10.y, ah1, al1);
            cvt_hilo(x02.x, x02.y, ah2, al2);
            cvt_hilo(x12.x, x12.y, ah3, al3);
            uint32_t bks = bbase + ks * 32;
            uint32_t bh0, bh1, bl0, bl1, nh0, nh1, nl0, nl1;
            lds64(bks, bh0, bh1);
            lds64(bks + K2_BLO, bl0, bl1);
            #pragma unroll
            for (int nt = 0; nt < 5; ++nt) {
                if (nt < 4) {
                    lds64(bks + (nt + 1) * 1280, nh0, nh1);
                    lds64(bks + (nt + 1) * 1280 + K2_BLO, nl0, nl1);
                }
                mma_bf16(acc[nt], ah0, ah1, ah2, ah3, bh0, bh1);
                mma_bf16(acc[nt], ah0, ah1, ah2, ah3, bl0, bl1);
                mma_bf16(acc[nt], al0, al1, al2, al3, bh0, bh1);
                bh0 = nh0; bh1 = nh1; bl0 = nl0; bl1 = nl1;
            }
        }

        // epilogue
        float s[10], ss[10];
        #pragma unroll
        for (int nt = 0; nt < 5; ++nt) {
            int col = nt * 8 + 2 * t;
            float v00 = acc[nt][0] + sb2[col];
            float v01 = acc[nt][1] + sb2[col + 1];
            float v10 = acc[nt][2] + sb2[col];
            float v11 = acc[nt][3] + sb2[col + 1];
            float2 o0; o0.x = v00; o0.y = v01;
            float2 o1; o1.x = v10; o1.y = v11;
            *(float2*)(g_h2 + (size_t)r0 * H2_ + col) = o0;
            *(float2*)(g_h2 + (size_t)r1 * H2_ + col) = o1;
            s[2 * nt]      = v00 + v10;
            ss[2 * nt]     = v00 * v00 + v10 * v10;
            s[2 * nt + 1]  = v01 + v11;
            ss[2 * nt + 1] = v01 * v01 + v11 * v11;
        }
        #pragma unroll
        for (int jj = 0; jj < 10; ++jj) {
            #pragma unroll
            for (int off = 4; off <= 16; off <<= 1) {
                s[jj]  += __shfl_xor_sync(0xffffffffu, s[jj],  off);
                ss[jj] += __shfl_xor_sync(0xffffffffu, ss[jj], off);
            }
        }
        float* rp = red + par * 640 + wid * 80;
        if (lid < 4) {
            #pragma unroll
            for (int nt = 0; nt < 5; ++nt) {
                int col = nt * 8 + 2 * lid;
                rp[col]          = s[2 * nt];
                rp[col + 1]      = s[2 * nt + 1];
                rp[40 + col]     = ss[2 * nt];
                rp[40 + col + 1] = ss[2 * nt + 1];
            }
        }
        __syncthreads();
        if (tid < H2_) {
            float S = 0.f, SS = 0.f;
            #pragma unroll
            for (int w = 0; w < 8; ++w) {
                S  += red[par * 640 + w * 80 + tid];
                SS += red[par * 640 + w * 80 + 40 + tid];
            }
            g_part2[tile * 80 + tid]      = S;
            g_part2[tile * 80 + 40 + tid] = SS;
        }
        par ^= 1;
    }
}

// ---------------- K3: smem-staged h2, scores + softmax + weighted key sum ----------------
__global__ void __launch_bounds__(256)
k3(const float* __restrict__ keys, const unsigned char* __restrict__ maskraw,
   const float* __restrict__ W3, const float* __restrict__ b3,
   const float* __restrict__ a2p, float* __restrict__ out) {
    __shared__ float sh2[T_ * 41];
    __shared__ float sw[H2_], sm2[H2_], sr2[H2_], sa2[H2_];
    __shared__ float sc[T_];
    __shared__ float red[256];
    __shared__ float osum[256];
    int b = blockIdx.x, tid = threadIdx.x;
    int mode = g_mask_mode;

    if (tid < H2_) {
        sw[tid]  = W3[tid];
        sm2[tid] = g_m2[tid];
        sr2[tid] = g_r2[tid];
        sa2[tid] = a2p[tid];
    }
    {
        const float4* src = (const float4*)(g_h2 + (size_t)b * T_ * H2_);
        for (int i = tid; i < T_ * 10; i += 256) {
            float4 v = src[i];
            int row = i / 10, c = (i - row * 10) * 4;
            float* d = sh2 + row * 41 + c;
            d[0] = v.x; d[1] = v.y; d[2] = v.z; d[3] = v.w;
        }
    }
    __syncthreads();

    if (tid < T_) {
        const float* hp = sh2 + tid * 41;
        float acc = b3[0];
        #pragma unroll
        for (int h = 0; h < H2_; ++h) {
            float x  = hp[h];
            float xn = (x - sm2[h]) * sr2[h];
            float p  = 1.f / (1.f + __expf(-xn));
            float al = sa2[h];
            acc += x * (al + p * (1.f - al)) * sw[h];
        }
        int idx = b * T_ + tid;
        bool mv;
        if (mode == 2)      mv = (((const float*)maskraw)[idx] != 0.0f);
        else if (mode == 1) mv = (((const int*)maskraw)[idx] != 0);
        else                mv = (maskraw[idx] != 0);
        sc[tid] = mv ? acc : PADV;
    }
    __syncthreads();

    red[tid] = (tid < T_) ? sc[tid] : -3.4e38f;
    __syncthreads();
    for (int st = 128; st > 0; st >>= 1) {
        if (tid < st) red[tid] = fmaxf(red[tid], red[tid + st]);
        __syncthreads();
    }
    float m = red[0];
    __syncthreads();

    float e = 0.f;
    if (tid < T_) e = __expf(sc[tid] - m);
    red[tid] = e;
    __syncthreads();
    for (int st = 128; st > 0; st >>= 1) {
        if (tid < st) red[tid] += red[tid + st];
        __syncthreads();
    }
    float inv = 1.0f / red[0];
    if (tid < T_) sc[tid] = e * inv;
    __syncthreads();

    int d = tid & 63, seg = tid >> 6;
    float acc2 = 0.f;
    const float* kp = keys + ((size_t)b * T_ + seg * 50) * 64 + d;
    #pragma unroll 5
    for (int t = 0; t < 50; ++t) acc2 += sc[seg * 50 + t] * kp[(size_t)t * 64];
    osum[tid] = acc2;
    __syncthreads();
    if (tid < 64)
        out[b * 64 + tid] =
            (osum[tid] + osum[64 + tid]) + (osum[128 + tid] + osum[192 + tid]);
}

// ---------------- launch ----------------
extern "C" void kernel_launch(void* const* d_in, const int* in_sizes, int n_in,
                              void* d_out, int out_size) {
    const float* queries = (const float*)d_in[0];
    const float* keys    = (const float*)d_in[1];
    const unsigned char* mask = (const unsigned char*)d_in[2];
    const float* W1 = (const float*)d_in[3];
    const float* b1 = (const float*)d_in[4];
    const float* a1 = (const float*)d_in[5];
    const float* W2 = (const float*)d_in[6];
    const float* b2 = (const float*)d_in[7];
    const float* a2 = (const float*)d_in[8];
    const float* W3 = (const float*)d_in[9];
    const float* b3 = (const float*)d_in[10];
    float* out = (float*)d_out;

    cudaFuncSetAttribute(k1, cudaFuncAttributeMaxDynamicSharedMemorySize, K1_SMEM);
    cudaFuncSetAttribute(k2, cudaFuncAttributeMaxDynamicSharedMemorySize, K2_SMEM);

    prep_all<<<54 + 128, 256>>>(queries, W1, W2, b1, mask);
    k1<<<PG1, 256, K1_SMEM>>>(keys, queries);
    stats1<<<H1_, 256>>>();
    k2<<<PG2, 256, K2_SMEM>>>(b2, a1);
    stats2<<<H2_, 256>>>();
    k3<<<B_, 256>>>(keys, mask, W3, b3, a2, out);
}

// round 14
// speedup vs baseline: 1.3992x; 1.3992x over previous
#include <cuda_runtime.h>
#include <cuda_bf16.h>
#include <cstdint>
#include <cstddef>

#define B_    2048
#define T_    200
#define H1_   80
#define H2_   40
#define NROWS (B_*T_)        // 409600
#define NT1   (NROWS/128)    // 3200 k1 tiles (128 rows)
#define NT2   (NROWS/128)    // 3200 k2 tiles (128 rows)
#define PG1   296
#define PG2   444
#define PADV  (-4294967296.0f)

// ---------------- device scratch ----------------
__device__ float g_h1[(size_t)NROWS*H1_];
__device__ float g_h2[(size_t)NROWS*H2_];
__device__ float g_qb[B_*H1_];
__device__ float g_part1[NT1*2*H1_];
__device__ float g_part2[NT2*2*H2_];
__device__ float g_m1[H1_], g_r1[H1_];
__device__ float g_m2[H2_], g_r2[H2_];
__device__ int   g_mask_mode;
// fragment-packed bf16 weight images (word = n*stride + ks*8 + t*2 + h)
__device__ __align__(16) uint32_t g_B1h[80*72], g_B1l[80*72];
__device__ __align__(16) uint32_t g_B2h[40*40], g_B2l[40*40];

// ---------------- helpers ----------------
__device__ __forceinline__ uint32_t smem_u32(const void* p) {
    uint32_t a;
    asm("{ .reg .u64 t; cvta.to.shared.u64 t, %1; cvt.u32.u64 %0, t; }"
        : "=r"(a) : "l"(p));
    return a;
}
__device__ __forceinline__ void lds64(uint32_t a, uint32_t& v0, uint32_t& v1) {
    asm volatile("ld.shared.v2.b32 {%0,%1}, [%2];" : "=r"(v0), "=r"(v1) : "r"(a));
}
__device__ __forceinline__ uint32_t pack_bf(float x0, float x1) { // x0 -> low
    uint32_t r;
    asm("cvt.rn.bf16x2.f32 %0, %1, %2;" : "=r"(r) : "f"(x1), "f"(x0));
    return r;
}
// truncation split: hi = x & 0xffff0000 (one PRMT packs both), lo = x - hi (exact)
__device__ __forceinline__ void cvt_hilo(float x0, float x1,
                                         uint32_t& hi, uint32_t& lo) {
    uint32_t u0 = __float_as_uint(x0), u1 = __float_as_uint(x1);
    hi = __byte_perm(u0, u1, 0x7632);
    float h0 = __uint_as_float(u0 & 0xffff0000u);
    float h1 = __uint_as_float(u1 & 0xffff0000u);
    lo = pack_bf(x0 - h0, x1 - h1);
}
__device__ __forceinline__ void mma_bf16(float* c,
                                         uint32_t a0, uint32_t a1, uint32_t a2, uint32_t a3,
                                         uint32_t b0, uint32_t b1) {
    asm volatile(
        "mma.sync.aligned.m16n8k16.row.col.f32.bf16.bf16.f32 "
        "{%0,%1,%2,%3}, {%4,%5,%6,%7}, {%8,%9}, {%0,%1,%2,%3};"
        : "+f"(c[0]), "+f"(c[1]), "+f"(c[2]), "+f"(c[3])
        : "r"(a0), "r"(a1), "r"(a2), "r"(a3), "r"(b0), "r"(b1));
}
__device__ __forceinline__ float dice1f(float v, float m, float r, float a) {
    float xn = (v - m) * r;
    float p  = 1.f / (1.f + __expf(-xn));
    return v * (a + p * (1.f - a));
}
__device__ __forceinline__ void frag_loc(int d, int& wof, int& pos) {
    int ks = d >> 4, kk = d & 15;
    int h = (kk >= 8) ? 1 : 0;
    int t = (kk & 7) >> 1;
    wof = ks * 8 + t * 2 + h;
    pos = kk & 1;
}

// ---------------- prep_all ----------------
// blocks: [0,40) B1 image, [40,53) B2 image, 53 mask, [54,182) qb (16 batches each)
__global__ void __launch_bounds__(256)
prep_all(const float* __restrict__ queries, const float* __restrict__ W1,
         const float* __restrict__ W2, const float* __restrict__ b1,
         const unsigned char* __restrict__ mask) {
    int blk = blockIdx.x, tid = threadIdx.x;
    if (blk < 40) {
        int i = blk * 256 + tid;
        int n = i >> 7, d = i & 127;
        float w;
        if (d < 64) w = W1[(64 + d) * H1_ + n] - W1[(128 + d) * H1_ + n];
        else        w = W1[(128 + d) * H1_ + n];
        __nv_bfloat16 h = __float2bfloat16(w);
        int wof, pos; frag_loc(d, wof, pos);
        *((__nv_bfloat16*)(g_B1h + n * 72 + wof) + pos) = h;
        *((__nv_bfloat16*)(g_B1l + n * 72 + wof) + pos) =
            __float2bfloat16(w - __bfloat162float(h));
    } else if (blk < 53) {
        int i = (blk - 40) * 256 + tid;
        if (i < H2_ * H1_) {
            int n = i / H1_, d = i - n * H1_;
            float w = W2[d * H2_ + n];
            __nv_bfloat16 h = __float2bfloat16(w);
            int wof, pos; frag_loc(d, wof, pos);
            *((__nv_bfloat16*)(g_B2h + n * 40 + wof) + pos) = h;
            *((__nv_bfloat16*)(g_B2l + n * 40 + wof) + pos) =
                __float2bfloat16(w - __bfloat162float(h));
        }
    } else if (blk == 53) {
        __shared__ int s_f32ok, s_i32ok, s_f32one, s_i32one;
        if (tid == 0) { s_f32ok = 1; s_i32ok = 1; s_f32one = 0; s_i32one = 0; }
        __syncthreads();
        const unsigned* w = (const unsigned*)mask;
        int f32ok = 1, i32ok = 1, f32one = 0, i32one = 0;
        for (int i = tid; i < 1024; i += 256) {
            unsigned v = w[i];
            if (v != 0u && v != 0x3F800000u) f32ok = 0;
            if (v == 0x3F800000u) f32one = 1;
            if (v != 0u && v != 1u) i32ok = 0;
            if (v == 1u) i32one = 1;
        }
        if (!f32ok) atomicAnd(&s_f32ok, 0);
        if (f32one) atomicOr(&s_f32one, 1);
        if (!i32ok) atomicAnd(&s_i32ok, 0);
        if (i32one) atomicOr(&s_i32one, 1);
        __syncthreads();
        if (tid == 0) {
            int mode = 0;
            if (s_f32ok && s_f32one)      mode = 2;
            else if (s_i32ok && s_i32one) mode = 1;
            g_mask_mode = mode;
        }
    } else {
        // qb: 16 batches per block, Wq staged once
        __shared__ float wq[64 * 80];
        __shared__ float qs[16][64];
        __shared__ float sb1[H1_];
        int pair = blk - 54;
        for (int i = tid; i < 64 * 80; i += 256)
            wq[i] = W1[i] + W1[128 * 80 + i];
        for (int i = tid; i < 16 * 64; i += 256)
            qs[i >> 6][i & 63] = queries[(size_t)(pair * 16) * 64 + i];
        if (tid < H1_) sb1[tid] = b1[tid];
        __syncthreads();
        #pragma unroll
        for (int w = 0; w < 5; ++w) {
            int work = tid + w * 256;           // 1280 outputs
            int j = work / H1_, h = work - j * H1_;
            float acc = sb1[h];
            #pragma unroll 8
            for (int d = 0; d < 64; ++d)
                acc += qs[j][d] * wq[d * 80 + h];
            g_qb[(pair * 16 + j) * H1_ + h] = acc;
        }
    }
}

// ---------------- K1: persistent, warp = 16 rows x 80 cols, 2 CTA/SM ----------------
// dyn smem: B_hi@0 (23040), B_lo@23040, red@46080 (2*8*160*4 = 10240) => 56320
#define K1_BLO  23040
#define K1_RED  46080
#define K1_SMEM 56320

__global__ void __launch_bounds__(256, 2)
k1(const float* __restrict__ keys, const float* __restrict__ queries) {
    extern __shared__ __align__(16) unsigned char smem[];
    uint32_t sb = smem_u32(smem);
    int tid = threadIdx.x, wid = tid >> 5, lid = tid & 31;
    int g = lid >> 2, t = lid & 3;

    {
        const uint4* s0 = (const uint4*)g_B1h;
        const uint4* s1 = (const uint4*)g_B1l;
        uint4* d0 = (uint4*)smem;
        uint4* d1 = (uint4*)(smem + K1_BLO);
        for (int i = tid; i < 1440; i += 256) { d0[i] = s0[i]; d1[i] = s1[i]; }
    }
    float* red = (float*)(smem + K1_RED);
    __syncthreads();

    int par = 0;
    for (int tile = blockIdx.x; tile < NT1; tile += PG1) {
        int row0 = tile * 128;
        int r0 = row0 + wid * 16 + g, r1 = r0 + 8;
        int br0 = r0 / T_, br1 = r1 / T_;
        const float* k0p = keys + (size_t)r0 * 64;
        const float* k1p = keys + (size_t)r1 * 64;
        const float* q0p = queries + (size_t)br0 * 64;
        const float* q1p = queries + (size_t)br1 * 64;

        float acc[10][4];
        #pragma unroll
        for (int nt = 0; nt < 10; ++nt)
            #pragma unroll
            for (int j = 0; j < 4; ++j) acc[nt][j] = 0.f;

        uint32_t bbase = sb + (uint32_t)g * 288 + t * 8;

        #pragma unroll
        for (int j = 0; j < 4; ++j) {
            int c0 = 2 * t + 16 * j, c1 = c0 + 8;
            float2 k00 = *(const float2*)(k0p + c0);
            float2 k02 = *(const float2*)(k0p + c1);
            float2 k10 = *(const float2*)(k1p + c0);
            float2 k12 = *(const float2*)(k1p + c1);
            #pragma unroll
            for (int half = 0; half < 2; ++half) {
                uint32_t ah0, al0, ah1, al1, ah2, al2, ah3, al3;
                if (half == 0) {
                    cvt_hilo(k00.x, k00.y, ah0, al0);
                    cvt_hilo(k10.x, k10.y, ah1, al1);
                    cvt_hilo(k02.x, k02.y, ah2, al2);
                    cvt_hilo(k12.x, k12.y, ah3, al3);
                } else {
                    float2 w00 = *(const float2*)(q0p + c0);
                    float2 w02 = *(const float2*)(q0p + c1);
                    float2 w10 = *(const float2*)(q1p + c0);
                    float2 w12 = *(const float2*)(q1p + c1);
                    cvt_hilo(k00.x * w00.x, k00.y * w00.y, ah0, al0);
                    cvt_hilo(k10.x * w10.x, k10.y * w10.y, ah1, al1);
                    cvt_hilo(k02.x * w02.x, k02.y * w02.y, ah2, al2);
                    cvt_hilo(k12.x * w12.x, k12.y * w12.y, ah3, al3);
                }
                uint32_t bks = bbase + (j + 4 * half) * 32;
                #pragma unroll
                for (int nt = 0; nt < 10; ++nt) {
                    uint32_t bh0, bh1, bl0, bl1;
                    lds64(bks + nt * 2304, bh0, bh1);
                    lds64(bks + nt * 2304 + K1_BLO, bl0, bl1);
                    mma_bf16(acc[nt], ah0, ah1, ah2, ah3, bh0, bh1);
                    mma_bf16(acc[nt], ah0, ah1, ah2, ah3, bl0, bl1);
                    mma_bf16(acc[nt], al0, al1, al2, al3, bh0, bh1);
                }
            }
        }

        // epilogue: qb add, STG h1, column stats
        float s[20], ss[20];
        const float* qb0 = g_qb + br0 * H1_;
        const float* qb1 = g_qb + br1 * H1_;
        #pragma unroll
        for (int nt = 0; nt < 10; ++nt) {
            int col = nt * 8 + 2 * t;
            float2 qa = *(const float2*)(qb0 + col);
            float2 qc = *(const float2*)(qb1 + col);
            float v00 = acc[nt][0] + qa.x, v01 = acc[nt][1] + qa.y;
            float v10 = acc[nt][2] + qc.x, v11 = acc[nt][3] + qc.y;
            float2 o0; o0.x = v00; o0.y = v01;
            float2 o1; o1.x = v10; o1.y = v11;
            *(float2*)(g_h1 + (size_t)r0 * H1_ + col) = o0;
            *(float2*)(g_h1 + (size_t)r1 * H1_ + col) = o1;
            s[2 * nt]      = v00 + v10;
            ss[2 * nt]     = v00 * v00 + v10 * v10;
            s[2 * nt + 1]  = v01 + v11;
            ss[2 * nt + 1] = v01 * v01 + v11 * v11;
        }
        #pragma unroll
        for (int jj = 0; jj < 20; ++jj) {
            #pragma unroll
            for (int off = 4; off <= 16; off <<= 1) {
                s[jj]  += __shfl_xor_sync(0xffffffffu, s[jj],  off);
                ss[jj] += __shfl_xor_sync(0xffffffffu, ss[jj], off);
            }
        }
        float* rp = red + par * 1280 + wid * 160;
        if (lid < 4) {
            #pragma unroll
            for (int nt = 0; nt < 10; ++nt) {
                int col = nt * 8 + 2 * lid;
                rp[col]          = s[2 * nt];
                rp[col + 1]      = s[2 * nt + 1];
                rp[80 + col]     = ss[2 * nt];
                rp[80 + col + 1] = ss[2 * nt + 1];
            }
        }
        __syncthreads();
        if (tid < H1_) {
            float S = 0.f, SS = 0.f;
            #pragma unroll
            for (int w = 0; w < 8; ++w) {
                S  += red[par * 1280 + w * 160 + tid];
                SS += red[par * 1280 + w * 160 + 80 + tid];
            }
            g_part1[tile * 160 + tid]      = S;
            g_part1[tile * 160 + 80 + tid] = SS;
        }
        par ^= 1;
    }
}

// ---------------- stats ----------------
__global__ void stats1() {
    __shared__ float rs[256], rss[256];
    int h = blockIdx.x, tid = threadIdx.x;
    float S = 0.f, SS = 0.f;
    for (int k = tid; k < NT1; k += 256) {
        S  += g_part1[k * 160 + h];
        SS += g_part1[k * 160 + 80 + h];
    }
    rs[tid] = S; rss[tid] = SS;
    __syncthreads();
    for (int st = 128; st > 0; st >>= 1) {
        if (tid < st) { rs[tid] += rs[tid + st]; rss[tid] += rss[tid + st]; }
        __syncthreads();
    }
    if (tid == 0) {
        float mean = rs[0] / (float)NROWS;
        float var  = rss[0] / (float)NROWS - mean * mean;
        g_m1[h] = mean;
        g_r1[h] = rsqrtf(fmaxf(var, 0.f) + 1e-8f);
    }
}
__global__ void stats2() {
    __shared__ float rs[256], rss[256];
    int h = blockIdx.x, tid = threadIdx.x;
    float S = 0.f, SS = 0.f;
    for (int k = tid; k < NT2; k += 256) {
        S  += g_part2[k * 80 + h];
        SS += g_part2[k * 80 + 40 + h];
    }
    rs[tid] = S; rss[tid] = SS;
    __syncthreads();
    for (int st = 128; st > 0; st >>= 1) {
        if (tid < st) { rs[tid] += rs[tid + st]; rss[tid] += rss[tid + st]; }
        __syncthreads();
    }
    if (tid == 0) {
        float mean = rs[0] / (float)NROWS;
        float var  = rss[0] / (float)NROWS - mean * mean;
        g_m2[h] = mean;
        g_r2[h] = rsqrtf(fmaxf(var, 0.f) + 1e-8f);
    }
}

// ---------------- K2: persistent, warp = 16 rows x 40 cols (3 CTA/SM) ----------------
// dyn smem: B2_hi@0 (6400), B2_lo@6400, red@12800 (2*8*80*4 = 5120) => 17920
#define K2_BLO  6400
#define K2_RED  12800
#define K2_SMEM 17920

__global__ void __launch_bounds__(256, 3)
k2(const float* __restrict__ b2, const float* __restrict__ a1) {
    extern __shared__ __align__(16) unsigned char smem[];
    __shared__ float pm[H1_], pr[H1_], pa[H1_], sb2[H2_];
    uint32_t sb = smem_u32(smem);
    int tid = threadIdx.x, wid = tid >> 5, lid = tid & 31;
    int g = lid >> 2, t = lid & 3;

    {
        const uint4* s0 = (const uint4*)g_B2h;
        const uint4* s1 = (const uint4*)g_B2l;
        uint4* d0 = (uint4*)smem;
        uint4* d1 = (uint4*)(smem + K2_BLO);
        for (int i = tid; i < 400; i += 256) { d0[i] = s0[i]; d1[i] = s1[i]; }
    }
    if (tid < H1_) { pm[tid] = g_m1[tid]; pr[tid] = g_r1[tid]; pa[tid] = a1[tid]; }
    if (tid >= 128 && tid < 128 + H2_) sb2[tid - 128] = b2[tid - 128];
    float* red = (float*)(smem + K2_RED);
    __syncthreads();

    int par = 0;
    for (int tile = blockIdx.x; tile < NT2; tile += PG2) {
        int row0 = tile * 128;
        int r0 = row0 + wid * 16 + g, r1 = r0 + 8;
        const float* h0p = g_h1 + (size_t)r0 * H1_;
        const float* h1p = g_h1 + (size_t)r1 * H1_;

        float acc[5][4];
        #pragma unroll
        for (int nt = 0; nt < 5; ++nt)
            #pragma unroll
            for (int j = 0; j < 4; ++j) acc[nt][j] = 0.f;

        uint32_t bbase = sb + (uint32_t)g * 160 + t * 8;

        #pragma unroll
        for (int ks = 0; ks < 5; ++ks) {
            int c0 = 2 * t + 16 * ks, c1 = c0 + 8;
            float2 x00 = *(const float2*)(h0p + c0);
            float2 x02 = *(const float2*)(h0p + c1);
            float2 x10 = *(const float2*)(h1p + c0);
            float2 x12 = *(const float2*)(h1p + c1);
            x00.x = dice1f(x00.x, pm[c0],     pr[c0],     pa[c0]);
            x00.y = dice1f(x00.y, pm[c0 + 1], pr[c0 + 1], pa[c0 + 1]);
            x02.x = dice1f(x02.x, pm[c1],     pr[c1],     pa[c1]);
            x02.y = dice1f(x02.y, pm[c1 + 1], pr[c1 + 1], pa[c1 + 1]);
            x10.x = dice1f(x10.x, pm[c0],     pr[c0],     pa[c0]);
            x10.y = dice1f(x10.y, pm[c0 + 1], pr[c0 + 1], pa[c0 + 1]);
            x12.x = dice1f(x12.x, pm[c1],     pr[c1],     pa[c1]);
            x12.y = dice1f(x12.y, pm[c1 + 1], pr[c1 + 1], pa[c1 + 1]);
            uint32_t ah0, al0, ah1, al1, ah2, al2, ah3, al3;
            cvt_hilo(x00.x, x00.y, ah0, al0);
            cvt_hilo(x10.x, x10.y, ah1, al1);
            cvt_hilo(x02.x, x02.y, ah2, al2);
            cvt_hilo(x12.x, x12.y, ah3, al3);
            uint32_t bks = bbase + ks * 32;
            uint32_t bh0, bh1, bl0, bl1, nh0, nh1, nl0, nl1;
            lds64(bks, bh0, bh1);
            lds64(bks + K2_BLO, bl0, bl1);
            #pragma unroll
            for (int nt = 0; nt < 5; ++nt) {
                if (nt < 4) {
                    lds64(bks + (nt + 1) * 1280, nh0, nh1);
                    lds64(bks + (nt + 1) * 1280 + K2_BLO, nl0, nl1);
                }
                mma_bf16(acc[nt], ah0, ah1, ah2, ah3, bh0, bh1);
                mma_bf16(acc[nt], ah0, ah1, ah2, ah3, bl0, bl1);
                mma_bf16(acc[nt], al0, al1, al2, al3, bh0, bh1);
                bh0 = nh0; bh1 = nh1; bl0 = nl0; bl1 = nl1;
            }
        }

        // epilogue
        float s[10], ss[10];
        #pragma unroll
        for (int nt = 0; nt < 5; ++nt) {
            int col = nt * 8 + 2 * t;
            float v00 = acc[nt][0] + sb2[col];
            float v01 = acc[nt][1] + sb2[col + 1];
            float v10 = acc[nt][2] + sb2[col];
            float v11 = acc[nt][3] + sb2[col + 1];
            float2 o0; o0.x = v00; o0.y = v01;
            float2 o1; o1.x = v10; o1.y = v11;
            *(float2*)(g_h2 + (size_t)r0 * H2_ + col) = o0;
            *(float2*)(g_h2 + (size_t)r1 * H2_ + col) = o1;
            s[2 * nt]      = v00 + v10;
            ss[2 * nt]     = v00 * v00 + v10 * v10;
            s[2 * nt + 1]  = v01 + v11;
            ss[2 * nt + 1] = v01 * v01 + v11 * v11;
        }
        #pragma unroll
        for (int jj = 0; jj < 10; ++jj) {
            #pragma unroll
            for (int off = 4; off <= 16; off <<= 1) {
                s[jj]  += __shfl_xor_sync(0xffffffffu, s[jj],  off);
                ss[jj] += __shfl_xor_sync(0xffffffffu, ss[jj], off);
            }
        }
        float* rp = red + par * 640 + wid * 80;
        if (lid < 4) {
            #pragma unroll
            for (int nt = 0; nt < 5; ++nt) {
                int col = nt * 8 + 2 * lid;
                rp[col]          = s[2 * nt];
                rp[col + 1]      = s[2 * nt + 1];
                rp[40 + col]     = ss[2 * nt];
                rp[40 + col + 1] = ss[2 * nt + 1];
            }
        }
        __syncthreads();
        if (tid < H2_) {
            float S = 0.f, SS = 0.f;
            #pragma unroll
            for (int w = 0; w < 8; ++w) {
                S  += red[par * 640 + w * 80 + tid];
                SS += red[par * 640 + w * 80 + 40 + tid];
            }
            g_part2[tile * 80 + tid]      = S;
            g_part2[tile * 80 + 40 + tid] = SS;
        }
        par ^= 1;
    }
}

// ---------------- K3: smem-staged h2, scores + softmax + weighted key sum ----------------
__global__ void __launch_bounds__(256)
k3(const float* __restrict__ keys, const unsigned char* __restrict__ maskraw,
   const float* __restrict__ W3, const float* __restrict__ b3,
   const float* __restrict__ a2p, float* __restrict__ out) {
    __shared__ float sh2[T_ * 41];      // 200x41 padded, 32.8 KB
    __shared__ float sw[H2_], sm2[H2_], sr2[H2_], sa2[H2_];
    __shared__ float sc[T_];
    __shared__ float red[256];
    __shared__ float osum[256];
    __shared__ float sb3;
    int b = blockIdx.x, tid = threadIdx.x;
    int mode = g_mask_mode;

    if (tid < H2_) {
        sw[tid]  = W3[tid];
        sm2[tid] = g_m2[tid];
        sr2[tid] = g_r2[tid];
        sa2[tid] = a2p[tid];
    }
    if (tid == 64) sb3 = b3[0];
    // coalesced float4 stage of this batch's h2 tile (200 rows x 40 cols = 2000 float4)
    {
        const float4* src = (const float4*)(g_h2 + (size_t)b * T_ * H2_);
        for (int i = tid; i < T_ * 10; i += 256) {
            float4 v = src[i];
            int row = i / 10, c = (i - row * 10) * 4;
            float* d = sh2 + row * 41 + c;
            d[0] = v.x; d[1] = v.y; d[2] = v.z; d[3] = v.w;
        }
    }
    __syncthreads();

    if (tid < T_) {
        const float* hp = sh2 + tid * 41;
        float acc = sb3;
        #pragma unroll
        for (int h = 0; h < H2_; ++h) {
            float x  = hp[h];
            float xn = (x - sm2[h]) * sr2[h];
            float p  = 1.f / (1.f + __expf(-xn));
            float al = sa2[h];
            acc += x * (al + p * (1.f - al)) * sw[h];
        }
        int idx = b * T_ + tid;
        bool mv;
        if (mode == 2)      mv = (((const float*)maskraw)[idx] != 0.0f);
        else if (mode == 1) mv = (((const int*)maskraw)[idx] != 0);
        else                mv = (maskraw[idx] != 0);
        sc[tid] = mv ? acc : PADV;
    }
    __syncthreads();

    red[tid] = (tid < T_) ? sc[tid] : -3.4e38f;
    __syncthreads();
    for (int st = 128; st > 0; st >>= 1) {
        if (tid < st) red[tid] = fmaxf(red[tid], red[tid + st]);
        __syncthreads();
    }
    float m = red[0];
    __syncthreads();

    float e = 0.f;
    if (tid < T_) e = __expf(sc[tid] - m);
    red[tid] = e;
    __syncthreads();
    for (int st = 128; st > 0; st >>= 1) {
        if (tid < st) red[tid] += red[tid + st];
        __syncthreads();
    }
    float inv = 1.0f / red[0];
    if (tid < T_) sc[tid] = e * inv;
    __syncthreads();

    int d = tid & 63, seg = tid >> 6;
    float acc2 = 0.f;
    const float* kp = keys + ((size_t)b * T_ + seg * 50) * 64 + d;
    #pragma unroll 5
    for (int t = 0; t < 50; ++t) acc2 += sc[seg * 50 + t] * kp[(size_t)t * 64];
    osum[tid] = acc2;
    __syncthreads();
    if (tid < 64)
        out[b * 64 + tid] =
            (osum[tid] + osum[64 + tid]) + (osum[128 + tid] + osum[192 + tid]);
}

// ---------------- launch ----------------
extern "C" void kernel_launch(void* const* d_in, const int* in_sizes, int n_in,
                              void* d_out, int out_size) {
    const float* queries = (const float*)d_in[0];
    const float* keys    = (const float*)d_in[1];
    const unsigned char* mask = (const unsigned char*)d_in[2];
    const float* W1 = (const float*)d_in[3];
    const float* b1 = (const float*)d_in[4];
    const float* a1 = (const float*)d_in[5];
    const float* W2 = (const float*)d_in[6];
    const float* b2 = (const float*)d_in[7];
    const float* a2 = (const float*)d_in[8];
    const float* W3 = (const float*)d_in[9];
    const float* b3 = (const float*)d_in[10];
    float* out = (float*)d_out;

    cudaFuncSetAttribute(k1, cudaFuncAttributeMaxDynamicSharedMemorySize, K1_SMEM);
    cudaFuncSetAttribute(k2, cudaFuncAttributeMaxDynamicSharedMemorySize, K2_SMEM);

    prep_all<<<54 + 128, 256>>>(queries, W1, W2, b1, mask);
    k1<<<PG1, 256, K1_SMEM>>>(keys, queries);
    stats1<<<H1_, 256>>>();
    k2<<<PG2, 256, K2_SMEM>>>(b2, a1);
    stats2<<<H2_, 256>>>();
    k3<<<B_, 256>>>(keys, mask, W3, b3, a2, out);
}